// round 15
// baseline (speedup 1.0000x reference)
#include <cuda_runtime.h>
#include <cuda_bf16.h>
#include <cstdint>

#define T_TOK 4096
#define H_DIM 1024
#define I_DIM 1024
#define E_NUM 8
#define S_SLOTS (T_TOK * 2)
#define BM 128
#define MAX_TILES (S_SLOTS / BM + E_NUM)   // 72
#define NCHUNK 32                          // K chunks of 32 elems (64B/row)
#define BLK_B 8192                         // one operand block: 128 rows x 64B

// ---------------- device scratch ----------------
__device__ int   d_counts[E_NUM];
__device__ int   d_expert_of_slot[S_SLOTS];
__device__ float d_w_of_slot[S_SLOTS];
__device__ int   d_perm[S_SLOTS];
__device__ int   d_tile_expert[MAX_TILES];
__device__ int   d_tile_row0[MAX_TILES];
__device__ int   d_tile_rowend[MAX_TILES];
__device__ int   d_num_tiles;
__device__ int   d_tile_flags[MAX_TILES];   // GEMM1 blocks done per tile
__device__ int   d_dnw_done;                // down-weight conversion blocks done
__device__ int   d_zero_done;               // out-zeroing blocks done

// block-chunked operands: [blockIdx][chunk] -> 8KB (128 rows x 64B, swizzled)
__device__ __align__(16) __nv_bfloat16 d_ag_h[(size_t)MAX_TILES * NCHUNK * 4096];
__device__ __align__(16) __nv_bfloat16 d_ag_l[(size_t)MAX_TILES * NCHUNK * 4096];
__device__ __align__(16) __nv_bfloat16 d_upwB_h[(size_t)E_NUM * 16 * NCHUNK * 4096];
__device__ __align__(16) __nv_bfloat16 d_upwB_l[(size_t)E_NUM * 16 * NCHUNK * 4096];
__device__ __align__(16) __nv_bfloat16 d_dnwB_h[(size_t)E_NUM * 8 * NCHUNK * 4096];
__device__ __align__(16) __nv_bfloat16 d_dnwB_l[(size_t)E_NUM * 8 * NCHUNK * 4096];
__device__ __align__(16) __nv_bfloat16 d_hbuf_h[(size_t)MAX_TILES * NCHUNK * 4096];
__device__ __align__(16) __nv_bfloat16 d_hbuf_l[(size_t)MAX_TILES * NCHUNK * 4096];

// ---------------- PTX helpers ----------------
__device__ __forceinline__ uint32_t smem_u32(const void* p) {
    uint32_t a;
    asm("{ .reg .u64 t; cvta.to.shared.u64 t, %1; cvt.u32.u64 %0, t; }" : "=r"(a) : "l"(p));
    return a;
}
#define MBAR_INIT(a, c) asm volatile("mbarrier.init.shared.b64 [%0], %1;" :: "r"(a), "r"(c) : "memory")
#define MBAR_EXPECT_TX(a, b) \
    asm volatile("mbarrier.arrive.expect_tx.shared.b64 _, [%0], %1;" :: "r"(a), "r"(b) : "memory")
#define MBAR_WAIT(a, ph) do {                                                            \
    uint32_t _m = (a), _p = (ph), _d;                                                    \
    asm volatile("{ .reg .pred p; mbarrier.try_wait.parity.acquire.cta.shared::cta.b64 " \
                 "p, [%1], %2; selp.b32 %0, 1, 0, p; }"                                  \
                 : "=r"(_d) : "r"(_m), "r"(_p) : "memory");                              \
    if (!_d) {                                                                           \
        asm volatile("{ .reg .pred P1; WL_%=: mbarrier.try_wait.parity.acquire.cta."     \
                     "shared::cta.b64 P1, [%0], %1, 0x989680; @P1 bra.uni WD_%=; "       \
                     "bra.uni WL_%=; WD_%=: }" :: "r"(_m), "r"(_p) : "memory");          \
    }                                                                                    \
} while (0)
#define BULK_G2S(dst, src, sz, mbar) \
    asm volatile("cp.async.bulk.shared::cluster.global.mbarrier::complete_tx::bytes " \
                 "[%0], [%1], %2, [%3];" :: "r"(dst), "l"(src), "r"(sz), "r"(mbar) : "memory")
#define BULK_S2G(gdst, ssrc, sz) \
    asm volatile("cp.async.bulk.global.shared::cta.bulk_group [%0], [%1], %2;" \
                 :: "l"(gdst), "r"(ssrc), "r"(sz) : "memory")
#define BULK_COMMIT() asm volatile("cp.async.bulk.commit_group;" ::: "memory")
#define BULK_WAIT0()  asm volatile("cp.async.bulk.wait_group 0;" ::: "memory")
#define FENCE_PROXY_ASYNC() asm volatile("fence.proxy.async.shared::cta;" ::: "memory")
#define LDSM_X4(r0, r1, r2, r3, addr) \
    asm volatile("ldmatrix.sync.aligned.m8n8.x4.shared.b16 {%0,%1,%2,%3}, [%4];" \
        : "=r"(r0), "=r"(r1), "=r"(r2), "=r"(r3) : "r"(addr))

__device__ __forceinline__ void mma_bf16(float* d, const uint32_t* a, uint32_t b0, uint32_t b1) {
    asm volatile("mma.sync.aligned.m16n8k16.row.col.f32.bf16.bf16.f32 "
        "{%0,%1,%2,%3}, {%4,%5,%6,%7}, {%8,%9}, {%0,%1,%2,%3};"
        : "+f"(d[0]), "+f"(d[1]), "+f"(d[2]), "+f"(d[3])
        : "r"(a[0]), "r"(a[1]), "r"(a[2]), "r"(a[3]), "r"(b0), "r"(b1));
}
__device__ __forceinline__ uint32_t packbf(float a, float b) {  // a->lo, b->hi
    uint32_t r;
    asm("cvt.rn.bf16x2.f32 %0, %1, %2;" : "=r"(r) : "f"(b), "f"(a));
    return r;
}
__device__ __forceinline__ float bf16r(float v) {
    return __bfloat162float(__float2bfloat16(v));
}

// split 32 fp32 -> hi/lo bf16 rows (64B each), store swizzled
__device__ __forceinline__ void store_split64(char* bh, char* bl, uint32_t off0,
                                              uint32_t swm, const float* v) {
    uint32_t hi[16], lo[16];
#pragma unroll
    for (int j = 0; j < 16; j++) {
        float a = v[2 * j], b = v[2 * j + 1];
        hi[j] = packbf(a, b);
        lo[j] = packbf(a - bf16r(a), b - bf16r(b));
    }
#pragma unroll
    for (int g = 0; g < 4; g++) {
        uint32_t o = (off0 + g * 16) ^ swm;
        *(uint4*)(bh + o) = make_uint4(hi[4 * g], hi[4 * g + 1], hi[4 * g + 2], hi[4 * g + 3]);
        *(uint4*)(bl + o) = make_uint4(lo[4 * g], lo[4 * g + 1], lo[4 * g + 2], lo[4 * g + 3]);
    }
}

// ---------------- router + sort ----------------
__global__ void zero_counts_kernel() {
    if (threadIdx.x < E_NUM) d_counts[threadIdx.x] = 0;
}
__global__ void router_kernel(const float* __restrict__ logits) {
    int t = blockIdx.x * blockDim.x + threadIdx.x;
    if (t >= T_TOK) return;
    float l[E_NUM];
#pragma unroll
    for (int e = 0; e < E_NUM; e++) l[e] = logits[t * E_NUM + e];
    int i0 = 0;
#pragma unroll
    for (int e = 1; e < E_NUM; e++) if (l[e] > l[i0]) i0 = e;
    int i1 = (i0 == 0) ? 1 : 0;
#pragma unroll
    for (int e = 0; e < E_NUM; e++) {
        if (e == i0 || e == i1) continue;
        if (l[e] > l[i1]) i1 = e;
    }
    float w0 = 1.f / (1.f + expf(l[i1] - l[i0]));
    d_expert_of_slot[2 * t] = i0; d_expert_of_slot[2 * t + 1] = i1;
    d_w_of_slot[2 * t] = w0;      d_w_of_slot[2 * t + 1] = 1.f - w0;
    atomicAdd(&d_counts[i0], 1);
    atomicAdd(&d_counts[i1], 1);
}
__global__ void setup_kernel() {
    __shared__ int s_off[E_NUM];
    __shared__ int s_cur[E_NUM];
    if (threadIdx.x < MAX_TILES) d_tile_flags[threadIdx.x] = 0;
    if (threadIdx.x == 0) { d_dnw_done = 0; d_zero_done = 0; }
    if (threadIdx.x == 0) {
        int acc = 0, nt = 0;
        for (int e = 0; e < E_NUM; e++) {
            int c = d_counts[e];
            s_off[e] = acc;
            for (int r = 0; r < c; r += BM) {
                d_tile_expert[nt] = e;
                d_tile_row0[nt] = acc + r;
                d_tile_rowend[nt] = acc + c;
                nt++;
            }
            acc += c;
        }
        d_num_tiles = nt;
    }
    if (threadIdx.x < E_NUM) s_cur[threadIdx.x] = 0;
    __syncthreads();
    for (int s = threadIdx.x; s < S_SLOTS; s += blockDim.x) {
        int e = d_expert_of_slot[s];
        int pos = s_off[e] + atomicAdd(&s_cur[e], 1);
        d_perm[pos] = s;
    }
}

// ---------------- prepass: gather_a + UP weights only (down/zero moved to GEMM)
#define G_A_BLKS (NCHUNK * MAX_TILES)        // 2304
#define G_UP_BLKS (16 * NCHUNK * E_NUM)      // 4096
#define G_TOTAL  (G_A_BLKS + G_UP_BLKS)      // 6400

__global__ void __launch_bounds__(128) prepass_kernel(const float* __restrict__ x,
                                                      const float* __restrict__ up_w) {
    const int b = blockIdx.x, tid = threadIdx.x;
    if (b < G_A_BLKS) {
        int tile = b >> 5;
        if (tile >= d_num_tiles) return;
        int c = b & 31;
        int r = tid;
        int row0 = d_tile_row0[tile], rowend = d_tile_rowend[tile];
        size_t blk = ((size_t)tile * NCHUNK + c) * BLK_B;
        char* bh = (char*)d_ag_h + blk;
        char* bl = (char*)d_ag_l + blk;
        uint32_t off0 = r * 64, swm = ((r >> 1) & 7) << 4;
        if (row0 + r < rowend) {
            int token = d_perm[row0 + r] >> 1;
            const float4* src = (const float4*)(x + (size_t)token * H_DIM + c * 32);
            float v[32];
#pragma unroll
            for (int j = 0; j < 8; j++) {
                float4 q = src[j];
                v[4 * j] = q.x; v[4 * j + 1] = q.y; v[4 * j + 2] = q.z; v[4 * j + 3] = q.w;
            }
            store_split64(bh, bl, off0, swm, v);
        } else {
            uint4 z = make_uint4(0, 0, 0, 0);
#pragma unroll
            for (int g = 0; g < 4; g++) {
                uint32_t o = (off0 + g * 16) ^ swm;
                *(uint4*)(bh + o) = z;
                *(uint4*)(bl + o) = z;
            }
        }
    } else {
        // ---- up/gate weights -> interleaved block layout ----
        int rem = b - G_A_BLKS;
        int e = rem >> 9;            // 512 blocks per expert
        int inner = rem & 511;
        int c = inner >> 4;
        int bx = inner & 15;
        int r = tid;
        const int N = 2 * I_DIM;
        const float* src = up_w + (size_t)e * H_DIM * N;
        int u = bx * 64 + (r >> 1);
        int ncol = (r & 1) ? I_DIM + u : u;
        size_t blk = (((size_t)e * 16 + bx) * NCHUNK + c) * BLK_B;
        char* bh = (char*)d_upwB_h + blk;
        char* bl = (char*)d_upwB_l + blk;
        float v[32];
#pragma unroll
        for (int j = 0; j < 32; j++) v[j] = src[(size_t)(c * 32 + j) * N + ncol];
        store_split64(bh, bl, r * 64, ((r >> 1) & 7) << 4, v);
    }
}

// ---------------- fused: G1 | dnw-convert | zero-out | G2 (flag-ordered) -------
#define STAGE_B 32768
#define MB_OFF  (3 * STAGE_B)
#define SMEM_B  (MB_OFF + 64)
#define G1_BLKS (16 * MAX_TILES)           // 1152
#define DNW_BLKS (8 * NCHUNK * E_NUM)      // 2048
#define Z_BLKS  2048
#define DNW0    G1_BLKS                    // 1152
#define Z0      (DNW0 + DNW_BLKS)          // 3200
#define G2_0    (Z0 + Z_BLKS)              // 5248
#define GEMM_TOTAL (G2_0 + 8 * MAX_TILES)  // 5824

__global__ void __launch_bounds__(128, 2) gemm_fused_kernel(float* __restrict__ out,
                                                            const float* __restrict__ dn_w) {
    const int b = blockIdx.x;
    const int tid = threadIdx.x, wid = tid >> 5, lane = tid & 31;

    // ---- light segment: down-weight conversion (overlaps G1 compute) ----
    if (b >= DNW0 && b < Z0) {
        int idx = b - DNW0;
        int e = idx >> 8;          // 256 blocks per expert
        int inner = idx & 255;
        int c = inner >> 3;
        int bxd = inner & 7;
        int r = tid;
        const float* src = dn_w + (size_t)e * I_DIM * H_DIM;
        int ncol = bxd * 128 + r;
        size_t blk = (((size_t)e * 8 + bxd) * NCHUNK + c) * BLK_B;
        char* bh = (char*)d_dnwB_h + blk;
        char* bl = (char*)d_dnwB_l + blk;
        float v[32];
#pragma unroll
        for (int j = 0; j < 32; j++) v[j] = src[(size_t)(c * 32 + j) * H_DIM + ncol];
        store_split64(bh, bl, r * 64, ((r >> 1) & 7) << 4, v);
        __threadfence();
        __syncthreads();
        if (tid == 0) atomicAdd(&d_dnw_done, 1);
        return;
    }
    // ---- light segment: zero out (overlaps G1 compute) ----
    if (b >= Z0 && b < G2_0) {
        size_t i0 = ((size_t)(b - Z0) * 128 + tid) * 4;
        float4* o = (float4*)out;
        float4 z = make_float4(0.f, 0.f, 0.f, 0.f);
#pragma unroll
        for (int j = 0; j < 4; j++) o[i0 + j] = z;
        __threadfence();
        __syncthreads();
        if (tid == 0) atomicAdd(&d_zero_done, 1);
        return;
    }

    const int G  = (b < G1_BLKS) ? 1 : 2;
    const int nb = (G == 1) ? (b & 15) : ((b - G2_0) & 7);
    const int tile = (G == 1) ? (b >> 4) : ((b - G2_0) >> 3);
    if (tile >= d_num_tiles) return;
    const int e = d_tile_expert[tile];
    const int row0 = d_tile_row0[tile];
    const int rowend = d_tile_rowend[tile];

    extern __shared__ char smem[];
    const uint32_t sb = smem_u32(smem);

    const char* Ah = (const char*)((G == 1) ? d_ag_h : d_hbuf_h) + (size_t)tile * NCHUNK * BLK_B;
    const char* Al = (const char*)((G == 1) ? d_ag_l : d_hbuf_l) + (size_t)tile * NCHUNK * BLK_B;
    const char* Bh;
    const char* Bl;
    if (G == 1) {
        size_t wb = ((size_t)e * 16 + nb) * NCHUNK * BLK_B;
        Bh = (const char*)d_upwB_h + wb; Bl = (const char*)d_upwB_l + wb;
    } else {
        size_t wb = ((size_t)e * 8 + nb) * NCHUNK * BLK_B;
        Bh = (const char*)d_dnwB_h + wb; Bl = (const char*)d_dnwB_l + wb;
    }

    if (tid == 0) {
#pragma unroll
        for (int s = 0; s < 3; s++) MBAR_INIT(sb + MB_OFF + s * 8, 1);
    }
    __syncthreads();

    auto fill = [&](int s, int c) {
        uint32_t mb = sb + MB_OFF + s * 8;
        uint32_t st = sb + s * STAGE_B;
        MBAR_EXPECT_TX(mb, (uint32_t)STAGE_B);
        BULK_G2S(st,          Ah + (size_t)c * BLK_B, (uint32_t)BLK_B, mb);
        BULK_G2S(st + 8192,   Al + (size_t)c * BLK_B, (uint32_t)BLK_B, mb);
        BULK_G2S(st + 16384,  Bh + (size_t)c * BLK_B, (uint32_t)BLK_B, mb);
        BULK_G2S(st + 24576,  Bl + (size_t)c * BLK_B, (uint32_t)BLK_B, mb);
    };
    if (tid == 0) {
        if (G == 2) {   // deps: tile's 16 G1 blocks + dnw conversion + zeroed out
            while (atomicAdd(&d_tile_flags[tile], 0) < 16 ||
                   atomicAdd(&d_dnw_done, 0) < DNW_BLKS ||
                   atomicAdd(&d_zero_done, 0) < Z_BLKS) __nanosleep(256);
            __threadfence();
        }
        fill(0, 0); fill(1, 1); fill(2, 2);
    }

    // ---- warp tiling: 2 m-warps x 2 n-warps; warp tile 64x64 ----
    const int warp_m = wid >> 1, warp_n = wid & 1;
    const int a_row = warp_m * 64 + (lane & 15);
    const uint32_t a_o0 = (uint32_t)(a_row * 64 + (lane >> 4) * 16);
    const uint32_t swm_a = (uint32_t)(((a_row >> 1) & 7) << 4);
    const int b_row = warp_n * 64 + ((lane >> 4) & 1) * 8 + (lane & 7);
    const uint32_t b_o0 = (uint32_t)(b_row * 64 + ((lane >> 3) & 1) * 16);
    const uint32_t swm_b = (uint32_t)(((b_row >> 1) & 7) << 4);

    float acc[4][8][4];
#pragma unroll
    for (int mt = 0; mt < 4; mt++)
#pragma unroll
        for (int nt = 0; nt < 8; nt++)
#pragma unroll
            for (int q = 0; q < 4; q++) acc[mt][nt][q] = 0.f;

    // ---- PROVEN mainloop: all LDSM results consumed by MMAs BEFORE barrier ----
    for (int c = 0; c < NCHUNK; c++) {
        const int s = c % 3;
        MBAR_WAIT(sb + MB_OFF + s * 8, (c / 3) & 1);
        const uint32_t st = sb + s * STAGE_B;
#pragma unroll
        for (int kb = 0; kb < 64; kb += 32) {
            uint32_t ah[4][4], al[4][4], bh[4][4], bl[4][4];
#pragma unroll
            for (int mt = 0; mt < 4; mt++) {
                uint32_t ao = (a_o0 + mt * 1024 + kb) ^ swm_a;
                LDSM_X4(ah[mt][0], ah[mt][1], ah[mt][2], ah[mt][3], st + ao);
                LDSM_X4(al[mt][0], al[mt][1], al[mt][2], al[mt][3], st + 8192 + ao);
            }
#pragma unroll
            for (int bp = 0; bp < 4; bp++) {
                uint32_t bo = (b_o0 + bp * 1024 + kb) ^ swm_b;
                LDSM_X4(bh[bp][0], bh[bp][1], bh[bp][2], bh[bp][3], st + 16384 + bo);
                LDSM_X4(bl[bp][0], bl[bp][1], bl[bp][2], bl[bp][3], st + 24576 + bo);
            }
#pragma unroll
            for (int mt = 0; mt < 4; mt++)
#pragma unroll
                for (int nt = 0; nt < 8; nt++)
                    mma_bf16(acc[mt][nt], ah[mt],
                             bh[nt >> 1][(nt & 1) * 2], bh[nt >> 1][(nt & 1) * 2 + 1]);
#pragma unroll
            for (int mt = 0; mt < 4; mt++)
#pragma unroll
                for (int nt = 0; nt < 8; nt++)
                    mma_bf16(acc[mt][nt], al[mt],
                             bh[nt >> 1][(nt & 1) * 2], bh[nt >> 1][(nt & 1) * 2 + 1]);
#pragma unroll
            for (int mt = 0; mt < 4; mt++)
#pragma unroll
                for (int nt = 0; nt < 8; nt++)
                    mma_bf16(acc[mt][nt], ah[mt],
                             bl[nt >> 1][(nt & 1) * 2], bl[nt >> 1][(nt & 1) * 2 + 1]);
        }
        __syncthreads();
        if (c + 3 < NCHUNK && tid == 0) fill(s, c + 3);
    }

    // ---- epilogue ----
    if (G == 1) {
        // stage h/l planes in smem (final block layout), then 2 bulk S2G stores
#pragma unroll
        for (int mt = 0; mt < 4; mt++) {
            int rA = warp_m * 64 + mt * 16 + (lane >> 2);   // local row
            int rB = rA + 8;
            uint32_t swA = ((uint32_t)(rA >> 1) & 7) << 4;
            uint32_t swB = ((uint32_t)(rB >> 1) & 7) << 4;
#pragma unroll
            for (int nt = 0; nt < 8; nt++) {
                int hcl = warp_n * 32 + nt * 4 + (lane & 3);   // local col in [0,64)
                uint32_t cblk = (uint32_t)(hcl >> 5) * 8192u;
                uint32_t coff = (uint32_t)(hcl & 31) * 2u;
                float* d = acc[mt][nt];
                {
                    float g = d[0], u = d[1];
                    float h = g / (1.f + expf(-g)) * u;
                    uint32_t o = cblk + (((uint32_t)rA * 64u + coff) ^ swA);
                    *(__nv_bfloat16*)(smem + o)         = __float2bfloat16(h);
                    *(__nv_bfloat16*)(smem + 16384 + o) = __float2bfloat16(h - bf16r(h));
                }
                {
                    float g = d[2], u = d[3];
                    float h = g / (1.f + expf(-g)) * u;
                    uint32_t o = cblk + (((uint32_t)rB * 64u + coff) ^ swB);
                    *(__nv_bfloat16*)(smem + o)         = __float2bfloat16(h);
                    *(__nv_bfloat16*)(smem + 16384 + o) = __float2bfloat16(h - bf16r(h));
                }
            }
        }
        __syncthreads();
        if (tid == 0) {
            FENCE_PROXY_ASYNC();
            char* gh = (char*)d_hbuf_h + ((size_t)tile * NCHUNK + nb * 2) * BLK_B;
            char* gl = (char*)d_hbuf_l + ((size_t)tile * NCHUNK + nb * 2) * BLK_B;
            BULK_S2G(gh, sb,          16384u);
            BULK_S2G(gl, sb + 16384u, 16384u);
            BULK_COMMIT();
            BULK_WAIT0();
            __threadfence();
            atomicAdd(&d_tile_flags[tile], 1);
        }
    } else {
        // scatter w*acc directly into out; exactly 2 commutative adds/element
#pragma unroll
        for (int mt = 0; mt < 4; mt++) {
            int rA = row0 + warp_m * 64 + mt * 16 + (lane >> 2);
            int rB = rA + 8;
            if (rA < rowend) {
                int slot = d_perm[rA];
                float w = d_w_of_slot[slot];
                float* po = out + (size_t)(slot >> 1) * H_DIM + nb * 128 + warp_n * 64 + 2 * (lane & 3);
#pragma unroll
                for (int nt = 0; nt < 8; nt++) {
                    float* d = acc[mt][nt];
                    atomicAdd(po + nt * 8,     w * d[0]);
                    atomicAdd(po + nt * 8 + 1, w * d[1]);
                }
            }
            if (rB < rowend) {
                int slot = d_perm[rB];
                float w = d_w_of_slot[slot];
                float* po = out + (size_t)(slot >> 1) * H_DIM + nb * 128 + warp_n * 64 + 2 * (lane & 3);
#pragma unroll
                for (int nt = 0; nt < 8; nt++) {
                    float* d = acc[mt][nt];
                    atomicAdd(po + nt * 8,     w * d[2]);
                    atomicAdd(po + nt * 8 + 1, w * d[3]);
                }
            }
        }
    }
}

// ---------------- launch ----------------
extern "C" void kernel_launch(void* const* d_in, const int* in_sizes, int n_in,
                              void* d_out, int out_size) {
    (void)in_sizes; (void)n_in; (void)out_size;
    const float* x      = (const float*)d_in[0];
    const float* logits = (const float*)d_in[1];
    const float* up_w   = (const float*)d_in[2];
    const float* down_w = (const float*)d_in[3];
    float* out = (float*)d_out;

    cudaFuncSetAttribute(gemm_fused_kernel, cudaFuncAttributeMaxDynamicSharedMemorySize, SMEM_B);

    zero_counts_kernel<<<1, 32>>>();                                   // 0
    router_kernel<<<T_TOK / 256, 256>>>(logits);                       // 1
    setup_kernel<<<1, 256>>>();                                        // 2 (zeroes flags)
    prepass_kernel<<<G_TOTAL, 128>>>(x, up_w);                         // 3 (A + up weights)
    gemm_fused_kernel<<<GEMM_TOTAL, 128, SMEM_B>>>(out, down_w);       // 4 (G1|dnw|zero|G2)
}

// round 16
// speedup vs baseline: 1.0294x; 1.0294x over previous
#include <cuda_runtime.h>
#include <cuda_bf16.h>
#include <cstdint>

#define T_TOK 4096
#define H_DIM 1024
#define I_DIM 1024
#define E_NUM 8
#define S_SLOTS (T_TOK * 2)
#define BM 128
#define MAX_TILES (S_SLOTS / BM + E_NUM)   // 72
#define NCHUNK 32                          // K chunks of 32 elems (64B/row)
#define BLK_B 8192                         // one operand block: 128 rows x 64B

// ---------------- device scratch ----------------
__device__ int   d_expert_of_slot[S_SLOTS];
__device__ float d_w_of_slot[S_SLOTS];
__device__ int   d_perm[S_SLOTS];
__device__ int   d_tile_expert[MAX_TILES];
__device__ int   d_tile_row0[MAX_TILES];
__device__ int   d_tile_rowend[MAX_TILES];
__device__ int   d_num_tiles;
__device__ int   d_tile_flags[MAX_TILES];   // GEMM1 blocks done per tile

// block-chunked operands: [blockIdx][chunk] -> 8KB (128 rows x 64B, swizzled)
__device__ __align__(16) __nv_bfloat16 d_ag_h[(size_t)MAX_TILES * NCHUNK * 4096];
__device__ __align__(16) __nv_bfloat16 d_ag_l[(size_t)MAX_TILES * NCHUNK * 4096];
__device__ __align__(16) __nv_bfloat16 d_upwB_h[(size_t)E_NUM * 16 * NCHUNK * 4096];
__device__ __align__(16) __nv_bfloat16 d_upwB_l[(size_t)E_NUM * 16 * NCHUNK * 4096];
__device__ __align__(16) __nv_bfloat16 d_dnwB_h[(size_t)E_NUM * 8 * NCHUNK * 4096];
__device__ __align__(16) __nv_bfloat16 d_dnwB_l[(size_t)E_NUM * 8 * NCHUNK * 4096];
__device__ __align__(16) __nv_bfloat16 d_hbuf_h[(size_t)MAX_TILES * NCHUNK * 4096];
__device__ __align__(16) __nv_bfloat16 d_hbuf_l[(size_t)MAX_TILES * NCHUNK * 4096];

// ---------------- PTX helpers ----------------
__device__ __forceinline__ uint32_t smem_u32(const void* p) {
    uint32_t a;
    asm("{ .reg .u64 t; cvta.to.shared.u64 t, %1; cvt.u32.u64 %0, t; }" : "=r"(a) : "l"(p));
    return a;
}
#define MBAR_INIT(a, c) asm volatile("mbarrier.init.shared.b64 [%0], %1;" :: "r"(a), "r"(c) : "memory")
#define MBAR_EXPECT_TX(a, b) \
    asm volatile("mbarrier.arrive.expect_tx.shared.b64 _, [%0], %1;" :: "r"(a), "r"(b) : "memory")
#define MBAR_WAIT(a, ph) do {                                                            \
    uint32_t _m = (a), _p = (ph), _d;                                                    \
    asm volatile("{ .reg .pred p; mbarrier.try_wait.parity.acquire.cta.shared::cta.b64 " \
                 "p, [%1], %2; selp.b32 %0, 1, 0, p; }"                                  \
                 : "=r"(_d) : "r"(_m), "r"(_p) : "memory");                              \
    if (!_d) {                                                                           \
        asm volatile("{ .reg .pred P1; WL_%=: mbarrier.try_wait.parity.acquire.cta."     \
                     "shared::cta.b64 P1, [%0], %1, 0x989680; @P1 bra.uni WD_%=; "       \
                     "bra.uni WL_%=; WD_%=: }" :: "r"(_m), "r"(_p) : "memory");          \
    }                                                                                    \
} while (0)
#define BULK_G2S(dst, src, sz, mbar) \
    asm volatile("cp.async.bulk.shared::cluster.global.mbarrier::complete_tx::bytes " \
                 "[%0], [%1], %2, [%3];" :: "r"(dst), "l"(src), "r"(sz), "r"(mbar) : "memory")
#define BULK_S2G(gdst, ssrc, sz) \
    asm volatile("cp.async.bulk.global.shared::cta.bulk_group [%0], [%1], %2;" \
                 :: "l"(gdst), "r"(ssrc), "r"(sz) : "memory")
#define BULK_COMMIT() asm volatile("cp.async.bulk.commit_group;" ::: "memory")
#define BULK_WAIT0()  asm volatile("cp.async.bulk.wait_group 0;" ::: "memory")
#define FENCE_PROXY_ASYNC() asm volatile("fence.proxy.async.shared::cta;" ::: "memory")
#define LDSM_X4(r0, r1, r2, r3, addr) \
    asm volatile("ldmatrix.sync.aligned.m8n8.x4.shared.b16 {%0,%1,%2,%3}, [%4];" \
        : "=r"(r0), "=r"(r1), "=r"(r2), "=r"(r3) : "r"(addr))

__device__ __forceinline__ void mma_bf16(float* d, const uint32_t* a, uint32_t b0, uint32_t b1) {
    asm volatile("mma.sync.aligned.m16n8k16.row.col.f32.bf16.bf16.f32 "
        "{%0,%1,%2,%3}, {%4,%5,%6,%7}, {%8,%9}, {%0,%1,%2,%3};"
        : "+f"(d[0]), "+f"(d[1]), "+f"(d[2]), "+f"(d[3])
        : "r"(a[0]), "r"(a[1]), "r"(a[2]), "r"(a[3]), "r"(b0), "r"(b1));
}
__device__ __forceinline__ uint32_t packbf(float a, float b) {  // a->lo, b->hi
    uint32_t r;
    asm("cvt.rn.bf16x2.f32 %0, %1, %2;" : "=r"(r) : "f"(b), "f"(a));
    return r;
}
__device__ __forceinline__ float bf16r(float v) {
    return __bfloat162float(__float2bfloat16(v));
}

// split 32 fp32 -> hi/lo bf16 rows (64B each), store swizzled
__device__ __forceinline__ void store_split64(char* bh, char* bl, uint32_t off0,
                                              uint32_t swm, const float* v) {
    uint32_t hi[16], lo[16];
#pragma unroll
    for (int j = 0; j < 16; j++) {
        float a = v[2 * j], b = v[2 * j + 1];
        hi[j] = packbf(a, b);
        lo[j] = packbf(a - bf16r(a), b - bf16r(b));
    }
#pragma unroll
    for (int g = 0; g < 4; g++) {
        uint32_t o = (off0 + g * 16) ^ swm;
        *(uint4*)(bh + o) = make_uint4(hi[4 * g], hi[4 * g + 1], hi[4 * g + 2], hi[4 * g + 3]);
        *(uint4*)(bl + o) = make_uint4(lo[4 * g], lo[4 * g + 1], lo[4 * g + 2], lo[4 * g + 3]);
    }
}

// ---------------- router (no global count atomics) ----------------
__global__ void router_kernel(const float* __restrict__ logits) {
    int t = blockIdx.x * blockDim.x + threadIdx.x;
    if (t >= T_TOK) return;
    float l[E_NUM];
#pragma unroll
    for (int e = 0; e < E_NUM; e++) l[e] = logits[t * E_NUM + e];
    int i0 = 0;
#pragma unroll
    for (int e = 1; e < E_NUM; e++) if (l[e] > l[i0]) i0 = e;
    int i1 = (i0 == 0) ? 1 : 0;
#pragma unroll
    for (int e = 0; e < E_NUM; e++) {
        if (e == i0 || e == i1) continue;
        if (l[e] > l[i1]) i1 = e;
    }
    float w0 = 1.f / (1.f + expf(l[i1] - l[i0]));
    d_expert_of_slot[2 * t] = i0; d_expert_of_slot[2 * t + 1] = i1;
    d_w_of_slot[2 * t] = w0;      d_w_of_slot[2 * t + 1] = 1.f - w0;
}

// ---------------- setup: counts (in smem) + offsets + tile map + scatter ------
__global__ void setup_kernel() {
    __shared__ int s_cnt[E_NUM];
    __shared__ int s_off[E_NUM];
    __shared__ int s_cur[E_NUM];
    const int tid = threadIdx.x;
    if (tid < MAX_TILES) d_tile_flags[tid] = 0;
    if (tid < E_NUM) { s_cnt[tid] = 0; s_cur[tid] = 0; }
    __syncthreads();
    for (int s = tid; s < S_SLOTS; s += blockDim.x)
        atomicAdd(&s_cnt[d_expert_of_slot[s]], 1);
    __syncthreads();
    if (tid == 0) {
        int acc = 0, nt = 0;
        for (int e = 0; e < E_NUM; e++) {
            int c = s_cnt[e];
            s_off[e] = acc;
            for (int r = 0; r < c; r += BM) {
                d_tile_expert[nt] = e;
                d_tile_row0[nt] = acc + r;
                d_tile_rowend[nt] = acc + c;
                nt++;
            }
            acc += c;
        }
        d_num_tiles = nt;
    }
    __syncthreads();
    for (int s = tid; s < S_SLOTS; s += blockDim.x) {
        int e = d_expert_of_slot[s];
        int pos = s_off[e] + atomicAdd(&s_cur[e], 1);
        d_perm[pos] = s;
    }
}

// ---------------- merged prepass: gather_a + conv_w + zero_out (round 14) ------
#define G_A_BLKS (NCHUNK * MAX_TILES)        // 2304
#define G_W_BLKS (24 * NCHUNK * E_NUM)       // 6144
#define G_Z_BLKS 2048
#define G_TOTAL  (G_A_BLKS + G_W_BLKS + G_Z_BLKS)   // 10496

__global__ void __launch_bounds__(128) prepass_kernel(const float* __restrict__ x,
                                                      const float* __restrict__ up_w,
                                                      const float* __restrict__ dn_w,
                                                      float* __restrict__ out) {
    const int b = blockIdx.x, tid = threadIdx.x;
    if (b < G_A_BLKS) {
        int tile = b >> 5;
        if (tile >= d_num_tiles) return;
        int c = b & 31;
        int r = tid;
        int row0 = d_tile_row0[tile], rowend = d_tile_rowend[tile];
        size_t blk = ((size_t)tile * NCHUNK + c) * BLK_B;
        char* bh = (char*)d_ag_h + blk;
        char* bl = (char*)d_ag_l + blk;
        uint32_t off0 = r * 64, swm = ((r >> 1) & 7) << 4;
        if (row0 + r < rowend) {
            int token = d_perm[row0 + r] >> 1;
            const float4* src = (const float4*)(x + (size_t)token * H_DIM + c * 32);
            float v[32];
#pragma unroll
            for (int j = 0; j < 8; j++) {
                float4 q = src[j];
                v[4 * j] = q.x; v[4 * j + 1] = q.y; v[4 * j + 2] = q.z; v[4 * j + 3] = q.w;
            }
            store_split64(bh, bl, off0, swm, v);
        } else {
            uint4 z = make_uint4(0, 0, 0, 0);
#pragma unroll
            for (int g = 0; g < 4; g++) {
                uint32_t o = (off0 + g * 16) ^ swm;
                *(uint4*)(bh + o) = z;
                *(uint4*)(bl + o) = z;
            }
        }
    } else if (b < G_A_BLKS + G_W_BLKS) {
        int rem = b - G_A_BLKS;
        int e = rem / (24 * NCHUNK);
        int r2 = rem % (24 * NCHUNK);
        int c = r2 / 24;
        int bx = r2 % 24;
        int r = tid;
        const float* src;
        char *bh, *bl;
        int N, ncol;
        if (bx < 16) {
            N = 2 * I_DIM;
            src = up_w + (size_t)e * H_DIM * N;
            int u = bx * 64 + (r >> 1);
            ncol = (r & 1) ? I_DIM + u : u;
            size_t blk = (((size_t)e * 16 + bx) * NCHUNK + c) * BLK_B;
            bh = (char*)d_upwB_h + blk; bl = (char*)d_upwB_l + blk;
        } else {
            N = H_DIM;
            src = dn_w + (size_t)e * I_DIM * N;
            ncol = (bx - 16) * 128 + r;
            size_t blk = (((size_t)e * 8 + (bx - 16)) * NCHUNK + c) * BLK_B;
            bh = (char*)d_dnwB_h + blk; bl = (char*)d_dnwB_l + blk;
        }
        float v[32];
#pragma unroll
        for (int j = 0; j < 32; j++) v[j] = src[(size_t)(c * 32 + j) * N + ncol];
        store_split64(bh, bl, r * 64, ((r >> 1) & 7) << 4, v);
    } else {
        size_t i0 = ((size_t)(b - G_A_BLKS - G_W_BLKS) * 128 + tid) * 4;
        float4* o = (float4*)out;
        float4 z = make_float4(0.f, 0.f, 0.f, 0.f);
#pragma unroll
        for (int j = 0; j < 4; j++) o[i0 + j] = z;
    }
}

// ---------------- fused GEMM1+GEMM2; G1 epilogue via smem-staged bulk store ----
#define STAGE_B 32768
#define MB_OFF  (3 * STAGE_B)
#define SMEM_B  (MB_OFF + 64)
#define G1_BLKS (16 * MAX_TILES)   // 1152
#define G2_BLKS (8 * MAX_TILES)    // 576

__global__ void __launch_bounds__(128, 2) gemm_fused_kernel(float* __restrict__ out) {
    const int b = blockIdx.x;
    const int tid = threadIdx.x, wid = tid >> 5, lane = tid & 31;

    const int G  = (b < G1_BLKS) ? 1 : 2;
    const int nb = (G == 1) ? (b & 15) : ((b - G1_BLKS) & 7);
    const int tile = (G == 1) ? (b >> 4) : ((b - G1_BLKS) >> 3);
    if (tile >= d_num_tiles) return;
    const int e = d_tile_expert[tile];
    const int row0 = d_tile_row0[tile];
    const int rowend = d_tile_rowend[tile];

    extern __shared__ char smem[];
    const uint32_t sb = smem_u32(smem);

    const char* Ah = (const char*)((G == 1) ? d_ag_h : d_hbuf_h) + (size_t)tile * NCHUNK * BLK_B;
    const char* Al = (const char*)((G == 1) ? d_ag_l : d_hbuf_l) + (size_t)tile * NCHUNK * BLK_B;
    const char* Bh;
    const char* Bl;
    if (G == 1) {
        size_t wb = ((size_t)e * 16 + nb) * NCHUNK * BLK_B;
        Bh = (const char*)d_upwB_h + wb; Bl = (const char*)d_upwB_l + wb;
    } else {
        size_t wb = ((size_t)e * 8 + nb) * NCHUNK * BLK_B;
        Bh = (const char*)d_dnwB_h + wb; Bl = (const char*)d_dnwB_l + wb;
    }

    if (tid == 0) {
#pragma unroll
        for (int s = 0; s < 3; s++) MBAR_INIT(sb + MB_OFF + s * 8, 1);
    }
    __syncthreads();

    auto fill = [&](int s, int c) {
        uint32_t mb = sb + MB_OFF + s * 8;
        uint32_t st = sb + s * STAGE_B;
        MBAR_EXPECT_TX(mb, (uint32_t)STAGE_B);
        BULK_G2S(st,          Ah + (size_t)c * BLK_B, (uint32_t)BLK_B, mb);
        BULK_G2S(st + 8192,   Al + (size_t)c * BLK_B, (uint32_t)BLK_B, mb);
        BULK_G2S(st + 16384,  Bh + (size_t)c * BLK_B, (uint32_t)BLK_B, mb);
        BULK_G2S(st + 24576,  Bl + (size_t)c * BLK_B, (uint32_t)BLK_B, mb);
    };
    if (tid == 0) {
        if (G == 2) {   // wait for this tile's 16 GEMM1 blocks before reading hbuf
            while (atomicAdd(&d_tile_flags[tile], 0) < 16) __nanosleep(256);
            __threadfence();
        }
        fill(0, 0); fill(1, 1); fill(2, 2);
    }

    // ---- warp tiling: 2 m-warps x 2 n-warps; warp tile 64x64 ----
    const int warp_m = wid >> 1, warp_n = wid & 1;
    const int a_row = warp_m * 64 + (lane & 15);
    const uint32_t a_o0 = (uint32_t)(a_row * 64 + (lane >> 4) * 16);
    const uint32_t swm_a = (uint32_t)(((a_row >> 1) & 7) << 4);
    const int b_row = warp_n * 64 + ((lane >> 4) & 1) * 8 + (lane & 7);
    const uint32_t b_o0 = (uint32_t)(b_row * 64 + ((lane >> 3) & 1) * 16);
    const uint32_t swm_b = (uint32_t)(((b_row >> 1) & 7) << 4);

    float acc[4][8][4];
#pragma unroll
    for (int mt = 0; mt < 4; mt++)
#pragma unroll
        for (int nt = 0; nt < 8; nt++)
#pragma unroll
            for (int q = 0; q < 4; q++) acc[mt][nt][q] = 0.f;

    // ---- PROVEN mainloop: all LDSM results consumed by MMAs BEFORE barrier ----
    for (int c = 0; c < NCHUNK; c++) {
        const int s = c % 3;
        MBAR_WAIT(sb + MB_OFF + s * 8, (c / 3) & 1);
        const uint32_t st = sb + s * STAGE_B;
#pragma unroll
        for (int kb = 0; kb < 64; kb += 32) {
            uint32_t ah[4][4], al[4][4], bh[4][4], bl[4][4];
#pragma unroll
            for (int mt = 0; mt < 4; mt++) {
                uint32_t ao = (a_o0 + mt * 1024 + kb) ^ swm_a;
                LDSM_X4(ah[mt][0], ah[mt][1], ah[mt][2], ah[mt][3], st + ao);
                LDSM_X4(al[mt][0], al[mt][1], al[mt][2], al[mt][3], st + 8192 + ao);
            }
#pragma unroll
            for (int bp = 0; bp < 4; bp++) {
                uint32_t bo = (b_o0 + bp * 1024 + kb) ^ swm_b;
                LDSM_X4(bh[bp][0], bh[bp][1], bh[bp][2], bh[bp][3], st + 16384 + bo);
                LDSM_X4(bl[bp][0], bl[bp][1], bl[bp][2], bl[bp][3], st + 24576 + bo);
            }
#pragma unroll
            for (int mt = 0; mt < 4; mt++)
#pragma unroll
                for (int nt = 0; nt < 8; nt++)
                    mma_bf16(acc[mt][nt], ah[mt],
                             bh[nt >> 1][(nt & 1) * 2], bh[nt >> 1][(nt & 1) * 2 + 1]);
#pragma unroll
            for (int mt = 0; mt < 4; mt++)
#pragma unroll
                for (int nt = 0; nt < 8; nt++)
                    mma_bf16(acc[mt][nt], al[mt],
                             bh[nt >> 1][(nt & 1) * 2], bh[nt >> 1][(nt & 1) * 2 + 1]);
#pragma unroll
            for (int mt = 0; mt < 4; mt++)
#pragma unroll
                for (int nt = 0; nt < 8; nt++)
                    mma_bf16(acc[mt][nt], ah[mt],
                             bl[nt >> 1][(nt & 1) * 2], bl[nt >> 1][(nt & 1) * 2 + 1]);
        }
        __syncthreads();
        if (c + 3 < NCHUNK && tid == 0) fill(s, c + 3);
    }

    // ---- epilogue ----
    if (G == 1) {
        // stage h/l planes in smem (final block layout), then 2 bulk S2G stores
#pragma unroll
        for (int mt = 0; mt < 4; mt++) {
            int rA = warp_m * 64 + mt * 16 + (lane >> 2);   // local row
            int rB = rA + 8;
            uint32_t swA = ((uint32_t)(rA >> 1) & 7) << 4;
            uint32_t swB = ((uint32_t)(rB >> 1) & 7) << 4;
#pragma unroll
            for (int nt = 0; nt < 8; nt++) {
                int hcl = warp_n * 32 + nt * 4 + (lane & 3);   // local col in [0,64)
                uint32_t cblk = (uint32_t)(hcl >> 5) * 8192u;
                uint32_t coff = (uint32_t)(hcl & 31) * 2u;
                float* d = acc[mt][nt];
                {
                    float g = d[0], u = d[1];
                    float h = g / (1.f + expf(-g)) * u;
                    uint32_t o = cblk + (((uint32_t)rA * 64u + coff) ^ swA);
                    *(__nv_bfloat16*)(smem + o)         = __float2bfloat16(h);
                    *(__nv_bfloat16*)(smem + 16384 + o) = __float2bfloat16(h - bf16r(h));
                }
                {
                    float g = d[2], u = d[3];
                    float h = g / (1.f + expf(-g)) * u;
                    uint32_t o = cblk + (((uint32_t)rB * 64u + coff) ^ swB);
                    *(__nv_bfloat16*)(smem + o)         = __float2bfloat16(h);
                    *(__nv_bfloat16*)(smem + 16384 + o) = __float2bfloat16(h - bf16r(h));
                }
            }
        }
        __syncthreads();
        if (tid == 0) {
            FENCE_PROXY_ASYNC();
            char* gh = (char*)d_hbuf_h + ((size_t)tile * NCHUNK + nb * 2) * BLK_B;
            char* gl = (char*)d_hbuf_l + ((size_t)tile * NCHUNK + nb * 2) * BLK_B;
            BULK_S2G(gh, sb,          16384u);
            BULK_S2G(gl, sb + 16384u, 16384u);
            BULK_COMMIT();
            BULK_WAIT0();
            __threadfence();
            atomicAdd(&d_tile_flags[tile], 1);
        }
    } else {
        // scatter w*acc directly into out; exactly 2 commutative adds/element
#pragma unroll
        for (int mt = 0; mt < 4; mt++) {
            int rA = row0 + warp_m * 64 + mt * 16 + (lane >> 2);
            int rB = rA + 8;
            if (rA < rowend) {
                int slot = d_perm[rA];
                float w = d_w_of_slot[slot];
                float* po = out + (size_t)(slot >> 1) * H_DIM + nb * 128 + warp_n * 64 + 2 * (lane & 3);
#pragma unroll
                for (int nt = 0; nt < 8; nt++) {
                    float* d = acc[mt][nt];
                    atomicAdd(po + nt * 8,     w * d[0]);
                    atomicAdd(po + nt * 8 + 1, w * d[1]);
                }
            }
            if (rB < rowend) {
                int slot = d_perm[rB];
                float w = d_w_of_slot[slot];
                float* po = out + (size_t)(slot >> 1) * H_DIM + nb * 128 + warp_n * 64 + 2 * (lane & 3);
#pragma unroll
                for (int nt = 0; nt < 8; nt++) {
                    float* d = acc[mt][nt];
                    atomicAdd(po + nt * 8,     w * d[2]);
                    atomicAdd(po + nt * 8 + 1, w * d[3]);
                }
            }
        }
    }
}

// ---------------- launch (round-14 proven structure, one launch fewer) --------
extern "C" void kernel_launch(void* const* d_in, const int* in_sizes, int n_in,
                              void* d_out, int out_size) {
    (void)in_sizes; (void)n_in; (void)out_size;
    const float* x      = (const float*)d_in[0];
    const float* logits = (const float*)d_in[1];
    const float* up_w   = (const float*)d_in[2];
    const float* down_w = (const float*)d_in[3];
    float* out = (float*)d_out;

    cudaFuncSetAttribute(gemm_fused_kernel, cudaFuncAttributeMaxDynamicSharedMemorySize, SMEM_B);

    router_kernel<<<T_TOK / 256, 256>>>(logits);                             // 0
    setup_kernel<<<1, 256>>>();                                              // 1 (counts+flags+map)
    prepass_kernel<<<G_TOTAL, 128>>>(x, up_w, down_w, out);                  // 2
    gemm_fused_kernel<<<G1_BLKS + G2_BLKS, 128, SMEM_B>>>(out);              // 3 (fused)
}